// round 14
// baseline (speedup 1.0000x reference)
#include <cuda_runtime.h>
#include <cuda_fp16.h>
#include <math.h>
#include <cstdint>

#define NE 160000
#define NN 10000

// ---------------- device scratch ----------------
__device__ __half g_Hh[(size_t)NE * 64];      // MLP hidden, fp16, [e][k]
__device__ __half g_w3T[(size_t)2816 * 64];   // w3 transposed [n][k], fp16
__device__ float g_sh[NE * 9];                // spherical harmonics
__device__ float g_cnt[NN];                   // per-node edge counts
__device__ float g_w3j[363];                  // Wigner-3j tables
__device__ __half g_Wv[(size_t)NE * 2816];    // per-edge weights (fp16, full)

// ---------------- path metadata ----------------
__device__ constexpr int PL1[11]   = {0,0,0,1,1,1,1,2,2,2,2};
__device__ constexpr int PL2[11]   = {0,1,2,0,1,1,2,0,1,2,2};
__device__ constexpr int PL3[11]   = {0,1,2,1,0,2,1,2,1,0,2};
__device__ constexpr int PD3[11]   = {1,3,5,3,1,5,3,5,3,1,5};
__device__ constexpr int W3OFF[11] = {0,1,10,35,44,53,98,143,168,213,238};
__device__ constexpr int TOFF[11]  = {0,16,64,144,192,208,288,336,416,464,480};
__device__ constexpr int AROW[11]  = {0,1,4,1,0,4,1,4,1,0,4};
__device__ constexpr float ALPHA[11] = {
    0.14433756729740643f, 0.21650635094610965f, 0.27950849718747373f,
    0.21650635094610965f, 0.14433756729740643f, 0.27950849718747373f,
    0.21650635094610965f, 0.27950849718747373f, 0.21650635094610965f,
    0.14433756729740643f, 0.27950849718747373f};
__device__ constexpr int XO[3] = {0,1,4};

// ---------------- mma.sync m16n8k16 fp16 -> fp32 ----------------
#define MMA_FP16(d, a, b) \
    asm volatile("mma.sync.aligned.m16n8k16.row.col.f32.f16.f16.f32 " \
        "{%0,%1,%2,%3}, {%4,%5,%6,%7}, {%8,%9}, {%0,%1,%2,%3};" \
        : "+f"((d)[0]), "+f"((d)[1]), "+f"((d)[2]), "+f"((d)[3]) \
        : "r"((a)[0]), "r"((a)[1]), "r"((a)[2]), "r"((a)[3]), \
          "r"((b)[0]), "r"((b)[1]))

// ---------------- W3J math (exact FP64 replica) ----------------
__device__ double dfact(int n) { double r = 1.0; for (int i = 2; i <= n; ++i) r *= (double)i; return r; }

__device__ double su2_cg(int j1, int m1, int j2, int m2, int j3, int m3) {
    if (m1 + m2 != m3) return 0.0;
    int vmin = 0;
    if (-j1 + j2 + m3 > vmin) vmin = -j1 + j2 + m3;
    if (-j1 + m1 > vmin)      vmin = -j1 + m1;
    int vmax = j2 + j3 + m1;
    if (j3 - j1 + j2 < vmax) vmax = j3 - j1 + j2;
    if (j3 + m3 < vmax)      vmax = j3 + m3;
    double C = sqrt((2.0 * j3 + 1.0) * dfact(j3 + j1 - j2) * dfact(j3 - j1 + j2) * dfact(j1 + j2 - j3)
                    / dfact(j1 + j2 + j3 + 1)
                    * dfact(j3 + m3) * dfact(j3 - m3)
                    / (dfact(j1 - m1) * dfact(j1 + m1) * dfact(j2 - m2) * dfact(j2 + m2)));
    double S = 0.0;
    for (int v = vmin; v <= vmax; ++v) {
        double sgn = ((v + j2 + m2) & 1) ? -1.0 : 1.0;
        S += sgn / dfact(v) * dfact(j2 + j3 + m1 - v) * dfact(j1 - m1 + v)
             / dfact(j3 - j1 + j2 - v) / dfact(j3 + m3 - v) / dfact(v + j1 - j2 - m3);
    }
    return C * S;
}

__device__ void qelem(int l, int r, int c, double& re, double& im) {
    int m = r - l;
    double vr = 0.0, vi = 0.0;
    const double is2 = 0.70710678118654752440;
    if (m < 0) {
        if (c == l - m) vr = is2;
        if (c == l + m) vi = -is2;
    } else if (m == 0) {
        if (c == l) vr = 1.0;
    } else {
        double sg = (m & 1) ? -1.0 : 1.0;
        if (c == l + m) vr = sg * is2;
        if (c == l - m) vi = sg * is2;
    }
    if (l == 1) { double t = vr; vr = vi; vi = -t; }
    else if (l == 2) { vr = -vr; vi = -vi; }
    re = vr; im = vi;
}

// ---------------- k_setup: w3j init (blocks 0..10) + zero/conv (blocks 11+) ----
__global__ void __launch_bounds__(512) k_setup(
    const float* __restrict__ w3, float* __restrict__ out)
{
    const int t = threadIdx.x;
    if (blockIdx.x < 11) {
        __shared__ double s_part[125 * 4];
        __shared__ double s_val[125];
        __shared__ double s_inv;
        const int p = blockIdx.x;
        const int l1 = PL1[p], l2 = PL2[p], l3 = PL3[p];
        const int d1 = 2 * l1 + 1, d2 = 2 * l2 + 1, d3 = 2 * l3 + 1;
        const int nel = d1 * d2 * d3;
        const int elem = t >> 2, part = t & 3;

        if (elem < nel) {
            const int j = elem / (d2 * d3);
            const int l = (elem / d3) % d2;
            const int m = elem % d3;
            double sre = 0.0;
            const int npair = d1 * d2;
            for (int pq = part; pq < npair; pq += 4) {
                const int i = pq / d2, k = pq % d2;
                const int n = (i - l1) + (k - l2) + l3;
                if (n < 0 || n >= d3) continue;
                const double cg = su2_cg(l1, i - l1, l2, k - l2, l3, n - l3);
                if (cg == 0.0) continue;
                double q1r, q1i, q2r, q2i, q3r, q3i;
                qelem(l1, i, j, q1r, q1i);
                qelem(l2, k, l, q2r, q2i);
                qelem(l3, n, m, q3r, q3i);
                q3i = -q3i;
                const double ar = q1r * q2r - q1i * q2i;
                const double ai = q1r * q2i + q1i * q2r;
                sre += (ar * q3r - ai * q3i) * cg;
            }
            s_part[elem * 4 + part] = sre;
        }
        __syncthreads();
        if (elem < nel && part == 0)
            s_val[elem] = s_part[elem * 4] + s_part[elem * 4 + 1]
                        + s_part[elem * 4 + 2] + s_part[elem * 4 + 3];
        __syncthreads();
        if (t == 0) {
            double n2 = 0.0;
            for (int q = 0; q < nel; ++q) n2 += s_val[q] * s_val[q];
            s_inv = 1.0 / sqrt(n2);
        }
        __syncthreads();
        if (elem < nel && part == 0)
            g_w3j[W3OFF[p] + elem] = (float)(s_val[elem] * s_inv);
    } else {
        const int i = (blockIdx.x - 11) * 512 + t;
        if (i < NN * 144) out[i] = 0.0f;
        if (i < NN) g_cnt[i] = 0.0f;
        if (i < 64 * 2816) {
            const int k = i / 2816, n = i % 2816;
            g_w3T[(size_t)n * 64 + k] = __float2half(w3[i]);
        }
    }
}

__global__ void k_div(float* __restrict__ out) {
    int i = blockIdx.x * blockDim.x + threadIdx.x;
    if (i < NN * 144) {
        float c = g_cnt[i / 144];
        out[i] = out[i] / fmaxf(c, 1.0f);
    }
}

// ---------------- kernel A: geometry + radial + MLP (+edge count) ----------------
__global__ void __launch_bounds__(256) k_edge_mlp(
    const float* __restrict__ pos, const int* __restrict__ batch,
    const int* __restrict__ esrc, const int* __restrict__ edst,
    const float* __restrict__ eshift, const float* __restrict__ cell,
    const float* __restrict__ w0, const float* __restrict__ b0,
    const float* __restrict__ w1, const float* __restrict__ b1,
    const float* __restrict__ w2, const float* __restrict__ b2)
{
    __shared__ float s_sh[4][4][9];
    __shared__ float s_emb[4][4][8];
    __shared__ float s_h0[4][4][64];
    __shared__ float s_h1[4][4][64];
    const int g = threadIdx.x >> 6;
    const int t = threadIdx.x & 63;
    const int eb = blockIdx.x * 16 + g * 4;

    if (t < 4) {
        const int e = eb + t;
        const int src = esrc[e], dst = edst[e];
        atomicAdd(&g_cnt[dst], 1.0f);          // folded k_count
        const int b = batch[src];
        const float s0 = eshift[e * 3 + 0], s1 = eshift[e * 3 + 1], s2 = eshift[e * 3 + 2];
        const float* C = cell + b * 9;
        float vx = pos[dst * 3 + 0] - pos[src * 3 + 0] + s0 * C[0] + s1 * C[3] + s2 * C[6];
        float vy = pos[dst * 3 + 1] - pos[src * 3 + 1] + s0 * C[1] + s1 * C[4] + s2 * C[7];
        float vz = pos[dst * 3 + 2] - pos[src * 3 + 2] + s0 * C[2] + s1 * C[5] + s2 * C[8];
        float r = sqrtf(vx * vx + vy * vy + vz * vz + 1e-12f);
        float ir = 1.0f / r;
        float x = vx * ir, y = vy * ir, z = vz * ir;
        const float s3c = 1.7320508075688772f;
        const float s15 = 3.8729833462074170f;
        const float s5  = 2.2360679774997896f;
        s_sh[g][t][0] = 1.0f;
        s_sh[g][t][1] = s3c * y;
        s_sh[g][t][2] = s3c * z;
        s_sh[g][t][3] = s3c * x;
        s_sh[g][t][4] = s15 * x * y;
        s_sh[g][t][5] = s15 * y * z;
        s_sh[g][t][6] = 0.5f * s5 * (3.0f * z * z - 1.0f);
        s_sh[g][t][7] = s15 * x * z;
        s_sh[g][t][8] = 0.5f * s15 * (x * x - y * y);
        float xr = fminf(fmaxf(r * (1.0f / 6.0f), 0.0f), 1.0f);
        float gate = (r <= 6.0f) ? 2.8284271247461903f : 0.0f;
        #pragma unroll
        for (int jb = 0; jb < 8; ++jb) {
            float d = (xr - (float)jb * (1.0f / 7.0f)) * 7.0f;
            s_emb[g][t][jb] = expf(-0.5f * d * d) * gate;
        }
    }
    __syncthreads();

    float a0, a1, a2, a3;
    {
        const float bv = b0[t];
        a0 = bv; a1 = bv; a2 = bv; a3 = bv;
        #pragma unroll
        for (int c = 0; c < 8; ++c) {
            const float w = w0[c * 64 + t];
            a0 += s_emb[g][0][c] * w;
            a1 += s_emb[g][1][c] * w;
            a2 += s_emb[g][2][c] * w;
            a3 += s_emb[g][3][c] * w;
        }
        a0 = a0 / (1.0f + expf(-a0));
        a1 = a1 / (1.0f + expf(-a1));
        a2 = a2 / (1.0f + expf(-a2));
        a3 = a3 / (1.0f + expf(-a3));
        s_h0[g][0][t] = a0; s_h0[g][1][t] = a1;
        s_h0[g][2][t] = a2; s_h0[g][3][t] = a3;
    }
    __syncthreads();

    {
        const float bv = b1[t];
        a0 = bv; a1 = bv; a2 = bv; a3 = bv;
        #pragma unroll 4
        for (int c4 = 0; c4 < 16; ++c4) {
            const float wa = w1[(c4 * 4 + 0) * 64 + t];
            const float wb = w1[(c4 * 4 + 1) * 64 + t];
            const float wc = w1[(c4 * 4 + 2) * 64 + t];
            const float wd = w1[(c4 * 4 + 3) * 64 + t];
            float4 h;
            h = *reinterpret_cast<const float4*>(&s_h0[g][0][c4 * 4]);
            a0 += h.x * wa + h.y * wb + h.z * wc + h.w * wd;
            h = *reinterpret_cast<const float4*>(&s_h0[g][1][c4 * 4]);
            a1 += h.x * wa + h.y * wb + h.z * wc + h.w * wd;
            h = *reinterpret_cast<const float4*>(&s_h0[g][2][c4 * 4]);
            a2 += h.x * wa + h.y * wb + h.z * wc + h.w * wd;
            h = *reinterpret_cast<const float4*>(&s_h0[g][3][c4 * 4]);
            a3 += h.x * wa + h.y * wb + h.z * wc + h.w * wd;
        }
        a0 = a0 / (1.0f + expf(-a0));
        a1 = a1 / (1.0f + expf(-a1));
        a2 = a2 / (1.0f + expf(-a2));
        a3 = a3 / (1.0f + expf(-a3));
        s_h1[g][0][t] = a0; s_h1[g][1][t] = a1;
        s_h1[g][2][t] = a2; s_h1[g][3][t] = a3;
    }
    __syncthreads();

    {
        const float bv = b2[t];
        a0 = bv; a1 = bv; a2 = bv; a3 = bv;
        #pragma unroll 4
        for (int c4 = 0; c4 < 16; ++c4) {
            const float wa = w2[(c4 * 4 + 0) * 64 + t];
            const float wb = w2[(c4 * 4 + 1) * 64 + t];
            const float wc = w2[(c4 * 4 + 2) * 64 + t];
            const float wd = w2[(c4 * 4 + 3) * 64 + t];
            float4 h;
            h = *reinterpret_cast<const float4*>(&s_h1[g][0][c4 * 4]);
            a0 += h.x * wa + h.y * wb + h.z * wc + h.w * wd;
            h = *reinterpret_cast<const float4*>(&s_h1[g][1][c4 * 4]);
            a1 += h.x * wa + h.y * wb + h.z * wc + h.w * wd;
            h = *reinterpret_cast<const float4*>(&s_h1[g][2][c4 * 4]);
            a2 += h.x * wa + h.y * wb + h.z * wc + h.w * wd;
            h = *reinterpret_cast<const float4*>(&s_h1[g][3][c4 * 4]);
            a3 += h.x * wa + h.y * wb + h.z * wc + h.w * wd;
        }
        a0 = a0 / (1.0f + expf(-a0));
        a1 = a1 / (1.0f + expf(-a1));
        a2 = a2 / (1.0f + expf(-a2));
        a3 = a3 / (1.0f + expf(-a3));
    }

    float av[4] = {a0, a1, a2, a3};
    #pragma unroll
    for (int ei = 0; ei < 4; ++ei)
        g_Hh[(size_t)(eb + ei) * 64 + t] = __float2half(av[ei]);
    if (t < 36) {
        const int ei = t / 9, c = t % 9;
        g_sh[(size_t)(eb + ei) * 9 + c] = s_sh[g][ei][c];
    }
}

// ---------------- kernel B1: HMMA GEMM fp16, smem-staged stores ----------------
#define TPAD 72
#define SPAD 136

__global__ void __launch_bounds__(256) k_gemm_mma(
    const float* __restrict__ b3)
{
    __shared__ __half smemBuf[2 * 128 * TPAD];
    __half* sA = smemBuf;
    __half* sB = smemBuf + 128 * TPAD;

    const int t  = threadIdx.x;
    const int n0 = blockIdx.x * 128;
    const int e0 = blockIdx.y * 128;

    {
        const uint4* gA = reinterpret_cast<const uint4*>(g_Hh + (size_t)e0 * 64);
        const uint4* gB = reinterpret_cast<const uint4*>(g_w3T + (size_t)n0 * 64);
        #pragma unroll
        for (int i = 0; i < 4; ++i) {
            int lin = t + i * 256;
            int row = lin >> 3, c8 = lin & 7;
            int dst = row * TPAD + c8 * 8;
            *reinterpret_cast<uint4*>(sA + dst) = gA[lin];
            *reinterpret_cast<uint4*>(sB + dst) = gB[lin];
        }
    }
    __syncthreads();

    const int lane = t & 31, wid = t >> 5;
    const int wm = wid & 3, wn = wid >> 2;
    const int g  = lane >> 2, tg = lane & 3;

    float acc[2][8][4];
    #pragma unroll
    for (int mi = 0; mi < 2; ++mi)
        #pragma unroll
        for (int ni = 0; ni < 8; ++ni)
            #pragma unroll
            for (int q = 0; q < 4; ++q) acc[mi][ni][q] = 0.0f;

    #pragma unroll
    for (int ks = 0; ks < 4; ++ks) {
        const int k0 = ks * 16;
        uint32_t ah[2][4];
        #pragma unroll
        for (int mi = 0; mi < 2; ++mi) {
            const int base = (wm * 32 + mi * 16 + g) * TPAD + k0 + tg * 2;
            ah[mi][0] = *reinterpret_cast<const uint32_t*>(sA + base);
            ah[mi][1] = *reinterpret_cast<const uint32_t*>(sA + base + 8 * TPAD);
            ah[mi][2] = *reinterpret_cast<const uint32_t*>(sA + base + 8);
            ah[mi][3] = *reinterpret_cast<const uint32_t*>(sA + base + 8 * TPAD + 8);
        }
        #pragma unroll
        for (int ni = 0; ni < 8; ++ni) {
            const int base = (wn * 64 + ni * 8 + g) * TPAD + k0 + tg * 2;
            uint32_t bh[2];
            bh[0] = *reinterpret_cast<const uint32_t*>(sB + base);
            bh[1] = *reinterpret_cast<const uint32_t*>(sB + base + 8);
            #pragma unroll
            for (int mi = 0; mi < 2; ++mi)
                MMA_FP16(acc[mi][ni], ah[mi], bh);
        }
    }

    __syncthreads();
    {
        __half* sC = smemBuf;
        #pragma unroll
        for (int mi = 0; mi < 2; ++mi) {
            const int rl = wm * 32 + mi * 16 + g;
            #pragma unroll
            for (int ni = 0; ni < 8; ++ni) {
                const int cl = wn * 64 + ni * 8 + tg * 2;
                const float2 bb = __ldg(reinterpret_cast<const float2*>(b3 + n0 + cl));
                *reinterpret_cast<__half2*>(sC + rl * SPAD + cl) =
                    __floats2half2_rn(acc[mi][ni][0] + bb.x, acc[mi][ni][1] + bb.y);
                *reinterpret_cast<__half2*>(sC + (rl + 8) * SPAD + cl) =
                    __floats2half2_rn(acc[mi][ni][2] + bb.x, acc[mi][ni][3] + bb.y);
            }
        }
    }
    __syncthreads();
    {
        const __half* sC = smemBuf;
        #pragma unroll
        for (int i = 0; i < 8; ++i) {
            const int lin = t + i * 256;
            const int row = lin >> 4, q = lin & 15;
            const uint4 v = *reinterpret_cast<const uint4*>(sC + row * SPAD + q * 8);
            *reinterpret_cast<uint4*>(&g_Wv[(size_t)(e0 + row) * 2816 + n0 + q * 8]) = v;
        }
    }
}

// ---------------- kernel B2: T-contraction + scatter (R12 form, occupancy-pinned) ----
__global__ void __launch_bounds__(256, 6) k_tp2(
    const float* __restrict__ f_in,
    const int* __restrict__ esrc, const int* __restrict__ edst,
    float* __restrict__ out)
{
    __shared__ float sT[16][560];
    __shared__ float ssh[16][9];
    __shared__ int   ssrc[16];
    __shared__ int   sdst[16];

    const int tid = threadIdx.x;
    const int e0  = blockIdx.x << 4;

    if (tid < 144) ssh[tid / 9][tid % 9] = g_sh[(size_t)e0 * 9 + tid];
    if (tid < 16) ssrc[tid] = esrc[e0 + tid];
    else if (tid < 32) sdst[tid - 16] = edst[e0 + tid - 16];
    __syncthreads();

    {
        const int e = tid >> 4, u = tid & 15;
        const float* x1 = f_in + (size_t)ssrc[e] * 144;
        float xall[9];
        xall[0] = x1[u];
        #pragma unroll
        for (int i = 0; i < 3; ++i) xall[1 + i] = x1[16 + i * 16 + u];
        #pragma unroll
        for (int i = 0; i < 5; ++i) xall[4 + i] = x1[64 + i * 16 + u];
        float sl[9];
        #pragma unroll
        for (int j = 0; j < 9; ++j) sl[j] = ssh[e][j];
        float* Te = sT[e];
        #pragma unroll
        for (int p = 0; p < 11; ++p) {
            const int l1 = PL1[p], l2 = PL2[p];
            const int d1 = 2 * l1 + 1, d2 = 2 * l2 + 1, d3 = PD3[p];
            float acc[5];
            #pragma unroll
            for (int k = 0; k < 5; ++k) acc[k] = 0.0f;
            const float* wj = g_w3j + W3OFF[p];
            #pragma unroll
            for (int i = 0; i < d1; ++i) {
                const float xi = xall[XO[l1] + i];
                #pragma unroll
                for (int j = 0; j < d2; ++j) {
                    const float xs = xi * sl[XO[l2] + j];
                    #pragma unroll
                    for (int k = 0; k < d3; ++k)
                        acc[k] += xs * __ldg(&wj[(i * d2 + j) * d3 + k]);
                }
            }
            #pragma unroll
            for (int k = 0; k < d3; ++k)
                Te[TOFF[p] + u * d3 + k] = ALPHA[p] * acc[k];
        }
    }
    __syncthreads();

    const int e  = tid >> 4;
    const int uh = (tid >> 2) & 3;
    const int wq = tid & 3;
    float4 acc[9];
    #pragma unroll
    for (int a = 0; a < 9; ++a) acc[a] = make_float4(0.f, 0.f, 0.f, 0.f);

    const __half* wvh = g_Wv + (size_t)(e0 + e) * 2816;
    const float* Te = sT[e];

    #pragma unroll
    for (int p = 0; p < 11; ++p) {
        const int d3 = PD3[p];
        #pragma unroll
        for (int ui = 0; ui < 4; ++ui) {
            const int u = uh * 4 + ui;
            const uint2 raw = *reinterpret_cast<const uint2*>(
                wvh + (p * 16 + u) * 16 + wq * 4);
            const float2 f0 = __half22float2(*reinterpret_cast<const __half2*>(&raw.x));
            const float2 f1 = __half22float2(*reinterpret_cast<const __half2*>(&raw.y));
            #pragma unroll
            for (int k = 0; k < d3; ++k) {
                const float tv = Te[TOFF[p] + u * d3 + k];
                const int a = AROW[p] + k;
                acc[a].x += tv * f0.x; acc[a].y += tv * f0.y;
                acc[a].z += tv * f1.x; acc[a].w += tv * f1.y;
            }
        }
    }

    #pragma unroll
    for (int a = 0; a < 9; ++a) {
        #pragma unroll
        for (int off = 4; off <= 8; off <<= 1) {
            acc[a].x += __shfl_xor_sync(0xffffffffu, acc[a].x, off);
            acc[a].y += __shfl_xor_sync(0xffffffffu, acc[a].y, off);
            acc[a].z += __shfl_xor_sync(0xffffffffu, acc[a].z, off);
            acc[a].w += __shfl_xor_sync(0xffffffffu, acc[a].w, off);
        }
    }
    if (uh == 0) {
        float* op = out + (size_t)sdst[e] * 144 + (wq << 2);
        #pragma unroll
        for (int a = 0; a < 9; ++a) {
            atomicAdd(op + a * 16 + 0, acc[a].x);
            atomicAdd(op + a * 16 + 1, acc[a].y);
            atomicAdd(op + a * 16 + 2, acc[a].z);
            atomicAdd(op + a * 16 + 3, acc[a].w);
        }
    }
}

// ---------------- launch ----------------
extern "C" void kernel_launch(void* const* d_in, const int* in_sizes, int n_in,
                              void* d_out, int out_size)
{
    const float* f_in   = (const float*)d_in[0];
    const float* pos    = (const float*)d_in[1];
    const int*   batch  = (const int*)d_in[3];
    const int*   esrc   = (const int*)d_in[4];
    const int*   edst   = (const int*)d_in[5];
    const float* eshift = (const float*)d_in[6];
    const float* cell   = (const float*)d_in[7];
    const float* w0 = (const float*)d_in[8];
    const float* b0 = (const float*)d_in[9];
    const float* w1 = (const float*)d_in[10];
    const float* b1 = (const float*)d_in[11];
    const float* w2 = (const float*)d_in[12];
    const float* b2 = (const float*)d_in[13];
    const float* w3 = (const float*)d_in[14];
    const float* b3 = (const float*)d_in[15];
    float* out = (float*)d_out;

    const int setup_blocks = 11 + (NN * 144 + 511) / 512;
    k_setup<<<setup_blocks, 512>>>(w3, out);
    k_edge_mlp<<<NE / 16, 256>>>(pos, batch, esrc, edst, eshift, cell,
                                 w0, b0, w1, b1, w2, b2);
    k_gemm_mma<<<dim3(22, NE / 128), 256>>>(b3);
    k_tp2<<<NE / 16, 256>>>(f_in, esrc, edst, out);
    k_div<<<(NN * 144 + 255) / 256, 256>>>(out);
}

// round 15
// speedup vs baseline: 1.3080x; 1.3080x over previous
#include <cuda_runtime.h>
#include <cuda_fp16.h>
#include <math.h>
#include <cstdint>

#define NE 160000
#define NN 10000

// ---------------- device scratch ----------------
__device__ __half g_Hh[(size_t)NE * 64];      // MLP hidden, fp16, [e][k]
__device__ __half g_w3T[(size_t)2816 * 64];   // w3 transposed [n][k], fp16
__device__ float g_sh[NE * 9];                // spherical harmonics
__device__ float g_cnt[NN];                   // per-node edge counts
__device__ float g_w3j[363];                  // Wigner-3j tables
__device__ __half g_Wv[(size_t)NE * 2816];    // per-edge weights (fp16, full)

// ---------------- path metadata ----------------
__device__ constexpr int PL1[11]   = {0,0,0,1,1,1,1,2,2,2,2};
__device__ constexpr int PL2[11]   = {0,1,2,0,1,1,2,0,1,2,2};
__device__ constexpr int PL3[11]   = {0,1,2,1,0,2,1,2,1,0,2};
__device__ constexpr int PD3[11]   = {1,3,5,3,1,5,3,5,3,1,5};
__device__ constexpr int W3OFF[11] = {0,1,10,35,44,53,98,143,168,213,238};
__device__ constexpr int TOFF[11]  = {0,16,64,144,192,208,288,336,416,464,480};
__device__ constexpr int AROW[11]  = {0,1,4,1,0,4,1,4,1,0,4};
__device__ constexpr float ALPHA[11] = {
    0.14433756729740643f, 0.21650635094610965f, 0.27950849718747373f,
    0.21650635094610965f, 0.14433756729740643f, 0.27950849718747373f,
    0.21650635094610965f, 0.27950849718747373f, 0.21650635094610965f,
    0.14433756729740643f, 0.27950849718747373f};
__device__ constexpr int XO[3] = {0,1,4};

// ---------------- mma.sync m16n8k16 fp16 -> fp32 ----------------
#define MMA_FP16(d, a, b) \
    asm volatile("mma.sync.aligned.m16n8k16.row.col.f32.f16.f16.f32 " \
        "{%0,%1,%2,%3}, {%4,%5,%6,%7}, {%8,%9}, {%0,%1,%2,%3};" \
        : "+f"((d)[0]), "+f"((d)[1]), "+f"((d)[2]), "+f"((d)[3]) \
        : "r"((a)[0]), "r"((a)[1]), "r"((a)[2]), "r"((a)[3]), \
          "r"((b)[0]), "r"((b)[1]))

// ---------------- W3J math (exact FP64 replica) ----------------
__device__ double dfact(int n) { double r = 1.0; for (int i = 2; i <= n; ++i) r *= (double)i; return r; }

__device__ double su2_cg(int j1, int m1, int j2, int m2, int j3, int m3) {
    if (m1 + m2 != m3) return 0.0;
    int vmin = 0;
    if (-j1 + j2 + m3 > vmin) vmin = -j1 + j2 + m3;
    if (-j1 + m1 > vmin)      vmin = -j1 + m1;
    int vmax = j2 + j3 + m1;
    if (j3 - j1 + j2 < vmax) vmax = j3 - j1 + j2;
    if (j3 + m3 < vmax)      vmax = j3 + m3;
    double C = sqrt((2.0 * j3 + 1.0) * dfact(j3 + j1 - j2) * dfact(j3 - j1 + j2) * dfact(j1 + j2 - j3)
                    / dfact(j1 + j2 + j3 + 1)
                    * dfact(j3 + m3) * dfact(j3 - m3)
                    / (dfact(j1 - m1) * dfact(j1 + m1) * dfact(j2 - m2) * dfact(j2 + m2)));
    double S = 0.0;
    for (int v = vmin; v <= vmax; ++v) {
        double sgn = ((v + j2 + m2) & 1) ? -1.0 : 1.0;
        S += sgn / dfact(v) * dfact(j2 + j3 + m1 - v) * dfact(j1 - m1 + v)
             / dfact(j3 - j1 + j2 - v) / dfact(j3 + m3 - v) / dfact(v + j1 - j2 - m3);
    }
    return C * S;
}

__device__ void qelem(int l, int r, int c, double& re, double& im) {
    int m = r - l;
    double vr = 0.0, vi = 0.0;
    const double is2 = 0.70710678118654752440;
    if (m < 0) {
        if (c == l - m) vr = is2;
        if (c == l + m) vi = -is2;
    } else if (m == 0) {
        if (c == l) vr = 1.0;
    } else {
        double sg = (m & 1) ? -1.0 : 1.0;
        if (c == l + m) vr = sg * is2;
        if (c == l - m) vi = sg * is2;
    }
    if (l == 1) { double t = vr; vr = vi; vi = -t; }
    else if (l == 2) { vr = -vr; vi = -vi; }
    re = vr; im = vi;
}

// ---------------- k_setup: w3j init (blocks 0..10) + zero/conv (blocks 11+) ----
__global__ void __launch_bounds__(512) k_setup(
    const float* __restrict__ w3, float* __restrict__ out)
{
    const int t = threadIdx.x;
    if (blockIdx.x < 11) {
        __shared__ double s_part[125 * 4];
        __shared__ double s_val[125];
        __shared__ double s_inv;
        const int p = blockIdx.x;
        const int l1 = PL1[p], l2 = PL2[p], l3 = PL3[p];
        const int d1 = 2 * l1 + 1, d2 = 2 * l2 + 1, d3 = 2 * l3 + 1;
        const int nel = d1 * d2 * d3;
        const int elem = t >> 2, part = t & 3;

        if (elem < nel) {
            const int j = elem / (d2 * d3);
            const int l = (elem / d3) % d2;
            const int m = elem % d3;
            double sre = 0.0;
            const int npair = d1 * d2;
            for (int pq = part; pq < npair; pq += 4) {
                const int i = pq / d2, k = pq % d2;
                const int n = (i - l1) + (k - l2) + l3;
                if (n < 0 || n >= d3) continue;
                const double cg = su2_cg(l1, i - l1, l2, k - l2, l3, n - l3);
                if (cg == 0.0) continue;
                double q1r, q1i, q2r, q2i, q3r, q3i;
                qelem(l1, i, j, q1r, q1i);
                qelem(l2, k, l, q2r, q2i);
                qelem(l3, n, m, q3r, q3i);
                q3i = -q3i;
                const double ar = q1r * q2r - q1i * q2i;
                const double ai = q1r * q2i + q1i * q2r;
                sre += (ar * q3r - ai * q3i) * cg;
            }
            s_part[elem * 4 + part] = sre;
        }
        __syncthreads();
        if (elem < nel && part == 0)
            s_val[elem] = s_part[elem * 4] + s_part[elem * 4 + 1]
                        + s_part[elem * 4 + 2] + s_part[elem * 4 + 3];
        __syncthreads();
        if (t == 0) {
            double n2 = 0.0;
            for (int q = 0; q < nel; ++q) n2 += s_val[q] * s_val[q];
            s_inv = 1.0 / sqrt(n2);
        }
        __syncthreads();
        if (elem < nel && part == 0)
            g_w3j[W3OFF[p] + elem] = (float)(s_val[elem] * s_inv);
    } else {
        const int i = (blockIdx.x - 11) * 512 + t;
        if (i < NN * 144) out[i] = 0.0f;
        if (i < NN) g_cnt[i] = 0.0f;
        if (i < 64 * 2816) {
            const int k = i / 2816, n = i % 2816;
            g_w3T[(size_t)n * 64 + k] = __float2half(w3[i]);
        }
    }
}

__global__ void k_div(float* __restrict__ out) {
    int i = blockIdx.x * blockDim.x + threadIdx.x;
    if (i < NN * 144) {
        float c = g_cnt[i / 144];
        out[i] = out[i] / fmaxf(c, 1.0f);
    }
}

// ---------------- kernel A: geometry + radial + MLP (+edge count) ----------------
__global__ void __launch_bounds__(256) k_edge_mlp(
    const float* __restrict__ pos, const int* __restrict__ batch,
    const int* __restrict__ esrc, const int* __restrict__ edst,
    const float* __restrict__ eshift, const float* __restrict__ cell,
    const float* __restrict__ w0, const float* __restrict__ b0,
    const float* __restrict__ w1, const float* __restrict__ b1,
    const float* __restrict__ w2, const float* __restrict__ b2)
{
    __shared__ float s_sh[4][4][9];
    __shared__ float s_emb[4][4][8];
    __shared__ float s_h0[4][4][64];
    __shared__ float s_h1[4][4][64];
    const int g = threadIdx.x >> 6;
    const int t = threadIdx.x & 63;
    const int eb = blockIdx.x * 16 + g * 4;

    if (t < 4) {
        const int e = eb + t;
        const int src = esrc[e], dst = edst[e];
        atomicAdd(&g_cnt[dst], 1.0f);          // folded k_count
        const int b = batch[src];
        const float s0 = eshift[e * 3 + 0], s1 = eshift[e * 3 + 1], s2 = eshift[e * 3 + 2];
        const float* C = cell + b * 9;
        float vx = pos[dst * 3 + 0] - pos[src * 3 + 0] + s0 * C[0] + s1 * C[3] + s2 * C[6];
        float vy = pos[dst * 3 + 1] - pos[src * 3 + 1] + s0 * C[1] + s1 * C[4] + s2 * C[7];
        float vz = pos[dst * 3 + 2] - pos[src * 3 + 2] + s0 * C[2] + s1 * C[5] + s2 * C[8];
        float r = sqrtf(vx * vx + vy * vy + vz * vz + 1e-12f);
        float ir = 1.0f / r;
        float x = vx * ir, y = vy * ir, z = vz * ir;
        const float s3c = 1.7320508075688772f;
        const float s15 = 3.8729833462074170f;
        const float s5  = 2.2360679774997896f;
        s_sh[g][t][0] = 1.0f;
        s_sh[g][t][1] = s3c * y;
        s_sh[g][t][2] = s3c * z;
        s_sh[g][t][3] = s3c * x;
        s_sh[g][t][4] = s15 * x * y;
        s_sh[g][t][5] = s15 * y * z;
        s_sh[g][t][6] = 0.5f * s5 * (3.0f * z * z - 1.0f);
        s_sh[g][t][7] = s15 * x * z;
        s_sh[g][t][8] = 0.5f * s15 * (x * x - y * y);
        float xr = fminf(fmaxf(r * (1.0f / 6.0f), 0.0f), 1.0f);
        float gate = (r <= 6.0f) ? 2.8284271247461903f : 0.0f;
        #pragma unroll
        for (int jb = 0; jb < 8; ++jb) {
            float d = (xr - (float)jb * (1.0f / 7.0f)) * 7.0f;
            s_emb[g][t][jb] = expf(-0.5f * d * d) * gate;
        }
    }
    __syncthreads();

    float a0, a1, a2, a3;
    {
        const float bv = b0[t];
        a0 = bv; a1 = bv; a2 = bv; a3 = bv;
        #pragma unroll
        for (int c = 0; c < 8; ++c) {
            const float w = w0[c * 64 + t];
            a0 += s_emb[g][0][c] * w;
            a1 += s_emb[g][1][c] * w;
            a2 += s_emb[g][2][c] * w;
            a3 += s_emb[g][3][c] * w;
        }
        a0 = a0 / (1.0f + expf(-a0));
        a1 = a1 / (1.0f + expf(-a1));
        a2 = a2 / (1.0f + expf(-a2));
        a3 = a3 / (1.0f + expf(-a3));
        s_h0[g][0][t] = a0; s_h0[g][1][t] = a1;
        s_h0[g][2][t] = a2; s_h0[g][3][t] = a3;
    }
    __syncthreads();

    {
        const float bv = b1[t];
        a0 = bv; a1 = bv; a2 = bv; a3 = bv;
        #pragma unroll 4
        for (int c4 = 0; c4 < 16; ++c4) {
            const float wa = w1[(c4 * 4 + 0) * 64 + t];
            const float wb = w1[(c4 * 4 + 1) * 64 + t];
            const float wc = w1[(c4 * 4 + 2) * 64 + t];
            const float wd = w1[(c4 * 4 + 3) * 64 + t];
            float4 h;
            h = *reinterpret_cast<const float4*>(&s_h0[g][0][c4 * 4]);
            a0 += h.x * wa + h.y * wb + h.z * wc + h.w * wd;
            h = *reinterpret_cast<const float4*>(&s_h0[g][1][c4 * 4]);
            a1 += h.x * wa + h.y * wb + h.z * wc + h.w * wd;
            h = *reinterpret_cast<const float4*>(&s_h0[g][2][c4 * 4]);
            a2 += h.x * wa + h.y * wb + h.z * wc + h.w * wd;
            h = *reinterpret_cast<const float4*>(&s_h0[g][3][c4 * 4]);
            a3 += h.x * wa + h.y * wb + h.z * wc + h.w * wd;
        }
        a0 = a0 / (1.0f + expf(-a0));
        a1 = a1 / (1.0f + expf(-a1));
        a2 = a2 / (1.0f + expf(-a2));
        a3 = a3 / (1.0f + expf(-a3));
        s_h1[g][0][t] = a0; s_h1[g][1][t] = a1;
        s_h1[g][2][t] = a2; s_h1[g][3][t] = a3;
    }
    __syncthreads();

    {
        const float bv = b2[t];
        a0 = bv; a1 = bv; a2 = bv; a3 = bv;
        #pragma unroll 4
        for (int c4 = 0; c4 < 16; ++c4) {
            const float wa = w2[(c4 * 4 + 0) * 64 + t];
            const float wb = w2[(c4 * 4 + 1) * 64 + t];
            const float wc = w2[(c4 * 4 + 2) * 64 + t];
            const float wd = w2[(c4 * 4 + 3) * 64 + t];
            float4 h;
            h = *reinterpret_cast<const float4*>(&s_h1[g][0][c4 * 4]);
            a0 += h.x * wa + h.y * wb + h.z * wc + h.w * wd;
            h = *reinterpret_cast<const float4*>(&s_h1[g][1][c4 * 4]);
            a1 += h.x * wa + h.y * wb + h.z * wc + h.w * wd;
            h = *reinterpret_cast<const float4*>(&s_h1[g][2][c4 * 4]);
            a2 += h.x * wa + h.y * wb + h.z * wc + h.w * wd;
            h = *reinterpret_cast<const float4*>(&s_h1[g][3][c4 * 4]);
            a3 += h.x * wa + h.y * wb + h.z * wc + h.w * wd;
        }
        a0 = a0 / (1.0f + expf(-a0));
        a1 = a1 / (1.0f + expf(-a1));
        a2 = a2 / (1.0f + expf(-a2));
        a3 = a3 / (1.0f + expf(-a3));
    }

    float av[4] = {a0, a1, a2, a3};
    #pragma unroll
    for (int ei = 0; ei < 4; ++ei)
        g_Hh[(size_t)(eb + ei) * 64 + t] = __float2half(av[ei]);
    if (t < 36) {
        const int ei = t / 9, c = t % 9;
        g_sh[(size_t)(eb + ei) * 9 + c] = s_sh[g][ei][c];
    }
}

// ---------------- kernel B1: HMMA GEMM fp16, smem-staged stores ----------------
#define TPAD 72
#define SPAD 136

__global__ void __launch_bounds__(256) k_gemm_mma(
    const float* __restrict__ b3)
{
    __shared__ __half smemBuf[2 * 128 * TPAD];
    __half* sA = smemBuf;
    __half* sB = smemBuf + 128 * TPAD;

    const int t  = threadIdx.x;
    const int n0 = blockIdx.x * 128;
    const int e0 = blockIdx.y * 128;

    {
        const uint4* gA = reinterpret_cast<const uint4*>(g_Hh + (size_t)e0 * 64);
        const uint4* gB = reinterpret_cast<const uint4*>(g_w3T + (size_t)n0 * 64);
        #pragma unroll
        for (int i = 0; i < 4; ++i) {
            int lin = t + i * 256;
            int row = lin >> 3, c8 = lin & 7;
            int dst = row * TPAD + c8 * 8;
            *reinterpret_cast<uint4*>(sA + dst) = gA[lin];
            *reinterpret_cast<uint4*>(sB + dst) = gB[lin];
        }
    }
    __syncthreads();

    const int lane = t & 31, wid = t >> 5;
    const int wm = wid & 3, wn = wid >> 2;
    const int g  = lane >> 2, tg = lane & 3;

    float acc[2][8][4];
    #pragma unroll
    for (int mi = 0; mi < 2; ++mi)
        #pragma unroll
        for (int ni = 0; ni < 8; ++ni)
            #pragma unroll
            for (int q = 0; q < 4; ++q) acc[mi][ni][q] = 0.0f;

    #pragma unroll
    for (int ks = 0; ks < 4; ++ks) {
        const int k0 = ks * 16;
        uint32_t ah[2][4];
        #pragma unroll
        for (int mi = 0; mi < 2; ++mi) {
            const int base = (wm * 32 + mi * 16 + g) * TPAD + k0 + tg * 2;
            ah[mi][0] = *reinterpret_cast<const uint32_t*>(sA + base);
            ah[mi][1] = *reinterpret_cast<const uint32_t*>(sA + base + 8 * TPAD);
            ah[mi][2] = *reinterpret_cast<const uint32_t*>(sA + base + 8);
            ah[mi][3] = *reinterpret_cast<const uint32_t*>(sA + base + 8 * TPAD + 8);
        }
        #pragma unroll
        for (int ni = 0; ni < 8; ++ni) {
            const int base = (wn * 64 + ni * 8 + g) * TPAD + k0 + tg * 2;
            uint32_t bh[2];
            bh[0] = *reinterpret_cast<const uint32_t*>(sB + base);
            bh[1] = *reinterpret_cast<const uint32_t*>(sB + base + 8);
            #pragma unroll
            for (int mi = 0; mi < 2; ++mi)
                MMA_FP16(acc[mi][ni], ah[mi], bh);
        }
    }

    __syncthreads();
    {
        __half* sC = smemBuf;
        #pragma unroll
        for (int mi = 0; mi < 2; ++mi) {
            const int rl = wm * 32 + mi * 16 + g;
            #pragma unroll
            for (int ni = 0; ni < 8; ++ni) {
                const int cl = wn * 64 + ni * 8 + tg * 2;
                const float2 bb = __ldg(reinterpret_cast<const float2*>(b3 + n0 + cl));
                *reinterpret_cast<__half2*>(sC + rl * SPAD + cl) =
                    __floats2half2_rn(acc[mi][ni][0] + bb.x, acc[mi][ni][1] + bb.y);
                *reinterpret_cast<__half2*>(sC + (rl + 8) * SPAD + cl) =
                    __floats2half2_rn(acc[mi][ni][2] + bb.x, acc[mi][ni][3] + bb.y);
            }
        }
    }
    __syncthreads();
    {
        const __half* sC = smemBuf;
        #pragma unroll
        for (int i = 0; i < 8; ++i) {
            const int lin = t + i * 256;
            const int row = lin >> 4, q = lin & 15;
            const uint4 v = *reinterpret_cast<const uint4*>(sC + row * SPAD + q * 8);
            *reinterpret_cast<uint4*>(&g_Wv[(size_t)(e0 + row) * 2816 + n0 + q * 8]) = v;
        }
    }
}

// ---------------- kernel B2: T-contraction + scatter (R12 form, no occupancy pin) ----
__global__ void __launch_bounds__(256) k_tp2(
    const float* __restrict__ f_in,
    const int* __restrict__ esrc, const int* __restrict__ edst,
    float* __restrict__ out)
{
    __shared__ float sT[16][560];
    __shared__ float ssh[16][9];
    __shared__ int   ssrc[16];
    __shared__ int   sdst[16];

    const int tid = threadIdx.x;
    const int e0  = blockIdx.x << 4;

    if (tid < 144) ssh[tid / 9][tid % 9] = g_sh[(size_t)e0 * 9 + tid];
    if (tid < 16) ssrc[tid] = esrc[e0 + tid];
    else if (tid < 32) sdst[tid - 16] = edst[e0 + tid - 16];
    __syncthreads();

    {
        const int e = tid >> 4, u = tid & 15;
        const float* x1 = f_in + (size_t)ssrc[e] * 144;
        float xall[9];
        xall[0] = x1[u];
        #pragma unroll
        for (int i = 0; i < 3; ++i) xall[1 + i] = x1[16 + i * 16 + u];
        #pragma unroll
        for (int i = 0; i < 5; ++i) xall[4 + i] = x1[64 + i * 16 + u];
        float sl[9];
        #pragma unroll
        for (int j = 0; j < 9; ++j) sl[j] = ssh[e][j];
        float* Te = sT[e];
        #pragma unroll
        for (int p = 0; p < 11; ++p) {
            const int l1 = PL1[p], l2 = PL2[p];
            const int d1 = 2 * l1 + 1, d2 = 2 * l2 + 1, d3 = PD3[p];
            float acc[5];
            #pragma unroll
            for (int k = 0; k < 5; ++k) acc[k] = 0.0f;
            const float* wj = g_w3j + W3OFF[p];
            #pragma unroll
            for (int i = 0; i < d1; ++i) {
                const float xi = xall[XO[l1] + i];
                #pragma unroll
                for (int j = 0; j < d2; ++j) {
                    const float xs = xi * sl[XO[l2] + j];
                    #pragma unroll
                    for (int k = 0; k < d3; ++k)
                        acc[k] += xs * __ldg(&wj[(i * d2 + j) * d3 + k]);
                }
            }
            #pragma unroll
            for (int k = 0; k < d3; ++k)
                Te[TOFF[p] + u * d3 + k] = ALPHA[p] * acc[k];
        }
    }
    __syncthreads();

    const int e  = tid >> 4;
    const int uh = (tid >> 2) & 3;
    const int wq = tid & 3;
    float4 acc[9];
    #pragma unroll
    for (int a = 0; a < 9; ++a) acc[a] = make_float4(0.f, 0.f, 0.f, 0.f);

    const __half* wvh = g_Wv + (size_t)(e0 + e) * 2816;
    const float* Te = sT[e];

    #pragma unroll
    for (int p = 0; p < 11; ++p) {
        const int d3 = PD3[p];
        #pragma unroll
        for (int ui = 0; ui < 4; ++ui) {
            const int u = uh * 4 + ui;
            const uint2 raw = *reinterpret_cast<const uint2*>(
                wvh + (p * 16 + u) * 16 + wq * 4);
            const float2 f0 = __half22float2(*reinterpret_cast<const __half2*>(&raw.x));
            const float2 f1 = __half22float2(*reinterpret_cast<const __half2*>(&raw.y));
            #pragma unroll
            for (int k = 0; k < d3; ++k) {
                const float tv = Te[TOFF[p] + u * d3 + k];
                const int a = AROW[p] + k;
                acc[a].x += tv * f0.x; acc[a].y += tv * f0.y;
                acc[a].z += tv * f1.x; acc[a].w += tv * f1.y;
            }
        }
    }

    #pragma unroll
    for (int a = 0; a < 9; ++a) {
        #pragma unroll
        for (int off = 4; off <= 8; off <<= 1) {
            acc[a].x += __shfl_xor_sync(0xffffffffu, acc[a].x, off);
            acc[a].y += __shfl_xor_sync(0xffffffffu, acc[a].y, off);
            acc[a].z += __shfl_xor_sync(0xffffffffu, acc[a].z, off);
            acc[a].w += __shfl_xor_sync(0xffffffffu, acc[a].w, off);
        }
    }
    if (uh == 0) {
        float* op = out + (size_t)sdst[e] * 144 + (wq << 2);
        #pragma unroll
        for (int a = 0; a < 9; ++a) {
            atomicAdd(op + a * 16 + 0, acc[a].x);
            atomicAdd(op + a * 16 + 1, acc[a].y);
            atomicAdd(op + a * 16 + 2, acc[a].z);
            atomicAdd(op + a * 16 + 3, acc[a].w);
        }
    }
}

// ---------------- launch ----------------
extern "C" void kernel_launch(void* const* d_in, const int* in_sizes, int n_in,
                              void* d_out, int out_size)
{
    const float* f_in   = (const float*)d_in[0];
    const float* pos    = (const float*)d_in[1];
    const int*   batch  = (const int*)d_in[3];
    const int*   esrc   = (const int*)d_in[4];
    const int*   edst   = (const int*)d_in[5];
    const float* eshift = (const float*)d_in[6];
    const float* cell   = (const float*)d_in[7];
    const float* w0 = (const float*)d_in[8];
    const float* b0 = (const float*)d_in[9];
    const float* w1 = (const float*)d_in[10];
    const float* b1 = (const float*)d_in[11];
    const float* w2 = (const float*)d_in[12];
    const float* b2 = (const float*)d_in[13];
    const float* w3 = (const float*)d_in[14];
    const float* b3 = (const float*)d_in[15];
    float* out = (float*)d_out;

    const int setup_blocks = 11 + (NN * 144 + 511) / 512;
    k_setup<<<setup_blocks, 512>>>(w3, out);
    k_edge_mlp<<<NE / 16, 256>>>(pos, batch, esrc, edst, eshift, cell,
                                 w0, b0, w1, b1, w2, b2);
    k_gemm_mma<<<dim3(22, NE / 128), 256>>>(b3);
    k_tp2<<<NE / 16, 256>>>(f_in, esrc, edst, out);
    k_div<<<(NN * 144 + 255) / 256, 256>>>(out);
}

// round 16
// speedup vs baseline: 1.3298x; 1.0167x over previous
#include <cuda_runtime.h>
#include <cuda_fp16.h>
#include <math.h>
#include <cstdint>

#define NE 160000
#define NN 10000

// ---------------- device scratch ----------------
__device__ __half g_Hh[(size_t)NE * 64];      // MLP hidden, fp16, [e][k]
__device__ __half g_w3T[(size_t)2816 * 64];   // w3 transposed [n][k], fp16
__device__ float g_sh[NE * 9];                // spherical harmonics
__device__ float g_cnt[NN];                   // per-node edge counts
__device__ float g_w3j[363];                  // Wigner-3j tables
__device__ __half g_Wv[(size_t)NE * 2816];    // per-edge weights (fp16, full)

// ---------------- path metadata ----------------
__device__ constexpr int PL1[11]   = {0,0,0,1,1,1,1,2,2,2,2};
__device__ constexpr int PL2[11]   = {0,1,2,0,1,1,2,0,1,2,2};
__device__ constexpr int PL3[11]   = {0,1,2,1,0,2,1,2,1,0,2};
__device__ constexpr int PD3[11]   = {1,3,5,3,1,5,3,5,3,1,5};
__device__ constexpr int W3OFF[11] = {0,1,10,35,44,53,98,143,168,213,238};
__device__ constexpr int TOFF[11]  = {0,16,64,144,192,208,288,336,416,464,480};
__device__ constexpr int AROW[11]  = {0,1,4,1,0,4,1,4,1,0,4};
__device__ constexpr float ALPHA[11] = {
    0.14433756729740643f, 0.21650635094610965f, 0.27950849718747373f,
    0.21650635094610965f, 0.14433756729740643f, 0.27950849718747373f,
    0.21650635094610965f, 0.27950849718747373f, 0.21650635094610965f,
    0.14433756729740643f, 0.27950849718747373f};
__device__ constexpr int XO[3] = {0,1,4};

// ---------------- mma.sync m16n8k16 fp16 -> fp32 ----------------
#define MMA_FP16(d, a, b) \
    asm volatile("mma.sync.aligned.m16n8k16.row.col.f32.f16.f16.f32 " \
        "{%0,%1,%2,%3}, {%4,%5,%6,%7}, {%8,%9}, {%0,%1,%2,%3};" \
        : "+f"((d)[0]), "+f"((d)[1]), "+f"((d)[2]), "+f"((d)[3]) \
        : "r"((a)[0]), "r"((a)[1]), "r"((a)[2]), "r"((a)[3]), \
          "r"((b)[0]), "r"((b)[1]))

// ---------------- W3J math (exact FP64 replica) ----------------
__device__ double dfact(int n) { double r = 1.0; for (int i = 2; i <= n; ++i) r *= (double)i; return r; }

__device__ double su2_cg(int j1, int m1, int j2, int m2, int j3, int m3) {
    if (m1 + m2 != m3) return 0.0;
    int vmin = 0;
    if (-j1 + j2 + m3 > vmin) vmin = -j1 + j2 + m3;
    if (-j1 + m1 > vmin)      vmin = -j1 + m1;
    int vmax = j2 + j3 + m1;
    if (j3 - j1 + j2 < vmax) vmax = j3 - j1 + j2;
    if (j3 + m3 < vmax)      vmax = j3 + m3;
    double C = sqrt((2.0 * j3 + 1.0) * dfact(j3 + j1 - j2) * dfact(j3 - j1 + j2) * dfact(j1 + j2 - j3)
                    / dfact(j1 + j2 + j3 + 1)
                    * dfact(j3 + m3) * dfact(j3 - m3)
                    / (dfact(j1 - m1) * dfact(j1 + m1) * dfact(j2 - m2) * dfact(j2 + m2)));
    double S = 0.0;
    for (int v = vmin; v <= vmax; ++v) {
        double sgn = ((v + j2 + m2) & 1) ? -1.0 : 1.0;
        S += sgn / dfact(v) * dfact(j2 + j3 + m1 - v) * dfact(j1 - m1 + v)
             / dfact(j3 - j1 + j2 - v) / dfact(j3 + m3 - v) / dfact(v + j1 - j2 - m3);
    }
    return C * S;
}

__device__ void qelem(int l, int r, int c, double& re, double& im) {
    int m = r - l;
    double vr = 0.0, vi = 0.0;
    const double is2 = 0.70710678118654752440;
    if (m < 0) {
        if (c == l - m) vr = is2;
        if (c == l + m) vi = -is2;
    } else if (m == 0) {
        if (c == l) vr = 1.0;
    } else {
        double sg = (m & 1) ? -1.0 : 1.0;
        if (c == l + m) vr = sg * is2;
        if (c == l - m) vi = sg * is2;
    }
    if (l == 1) { double t = vr; vr = vi; vi = -t; }
    else if (l == 2) { vr = -vr; vi = -vi; }
    re = vr; im = vi;
}

// ---------------- k_setup: w3j init (blocks 0..10) + zero/conv (blocks 11+) ----
__global__ void __launch_bounds__(512) k_setup(
    const float* __restrict__ w3, float* __restrict__ out)
{
    const int t = threadIdx.x;
    if (blockIdx.x < 11) {
        __shared__ double s_part[125 * 4];
        __shared__ double s_val[125];
        __shared__ double s_inv;
        const int p = blockIdx.x;
        const int l1 = PL1[p], l2 = PL2[p], l3 = PL3[p];
        const int d1 = 2 * l1 + 1, d2 = 2 * l2 + 1, d3 = 2 * l3 + 1;
        const int nel = d1 * d2 * d3;
        const int elem = t >> 2, part = t & 3;

        if (elem < nel) {
            const int j = elem / (d2 * d3);
            const int l = (elem / d3) % d2;
            const int m = elem % d3;
            double sre = 0.0;
            const int npair = d1 * d2;
            for (int pq = part; pq < npair; pq += 4) {
                const int i = pq / d2, k = pq % d2;
                const int n = (i - l1) + (k - l2) + l3;
                if (n < 0 || n >= d3) continue;
                const double cg = su2_cg(l1, i - l1, l2, k - l2, l3, n - l3);
                if (cg == 0.0) continue;
                double q1r, q1i, q2r, q2i, q3r, q3i;
                qelem(l1, i, j, q1r, q1i);
                qelem(l2, k, l, q2r, q2i);
                qelem(l3, n, m, q3r, q3i);
                q3i = -q3i;
                const double ar = q1r * q2r - q1i * q2i;
                const double ai = q1r * q2i + q1i * q2r;
                sre += (ar * q3r - ai * q3i) * cg;
            }
            s_part[elem * 4 + part] = sre;
        }
        __syncthreads();
        if (elem < nel && part == 0)
            s_val[elem] = s_part[elem * 4] + s_part[elem * 4 + 1]
                        + s_part[elem * 4 + 2] + s_part[elem * 4 + 3];
        __syncthreads();
        if (t == 0) {
            double n2 = 0.0;
            for (int q = 0; q < nel; ++q) n2 += s_val[q] * s_val[q];
            s_inv = 1.0 / sqrt(n2);
        }
        __syncthreads();
        if (elem < nel && part == 0)
            g_w3j[W3OFF[p] + elem] = (float)(s_val[elem] * s_inv);
    } else {
        const int i = (blockIdx.x - 11) * 512 + t;
        if (i < NN * 144) out[i] = 0.0f;
        if (i < NN) g_cnt[i] = 0.0f;
        if (i < 64 * 2816) {
            const int k = i / 2816, n = i % 2816;
            g_w3T[(size_t)n * 64 + k] = __float2half(w3[i]);
        }
    }
}

// ---------------- kernel A: geometry + radial + MLP (+edge count) ----------------
__global__ void __launch_bounds__(256) k_edge_mlp(
    const float* __restrict__ pos, const int* __restrict__ batch,
    const int* __restrict__ esrc, const int* __restrict__ edst,
    const float* __restrict__ eshift, const float* __restrict__ cell,
    const float* __restrict__ w0, const float* __restrict__ b0,
    const float* __restrict__ w1, const float* __restrict__ b1,
    const float* __restrict__ w2, const float* __restrict__ b2)
{
    __shared__ float s_sh[4][4][9];
    __shared__ float s_emb[4][4][8];
    __shared__ float s_h0[4][4][64];
    __shared__ float s_h1[4][4][64];
    const int g = threadIdx.x >> 6;
    const int t = threadIdx.x & 63;
    const int eb = blockIdx.x * 16 + g * 4;

    if (t < 4) {
        const int e = eb + t;
        const int src = esrc[e], dst = edst[e];
        atomicAdd(&g_cnt[dst], 1.0f);          // folded k_count
        const int b = batch[src];
        const float s0 = eshift[e * 3 + 0], s1 = eshift[e * 3 + 1], s2 = eshift[e * 3 + 2];
        const float* C = cell + b * 9;
        float vx = pos[dst * 3 + 0] - pos[src * 3 + 0] + s0 * C[0] + s1 * C[3] + s2 * C[6];
        float vy = pos[dst * 3 + 1] - pos[src * 3 + 1] + s0 * C[1] + s1 * C[4] + s2 * C[7];
        float vz = pos[dst * 3 + 2] - pos[src * 3 + 2] + s0 * C[2] + s1 * C[5] + s2 * C[8];
        float r = sqrtf(vx * vx + vy * vy + vz * vz + 1e-12f);
        float ir = 1.0f / r;
        float x = vx * ir, y = vy * ir, z = vz * ir;
        const float s3c = 1.7320508075688772f;
        const float s15 = 3.8729833462074170f;
        const float s5  = 2.2360679774997896f;
        s_sh[g][t][0] = 1.0f;
        s_sh[g][t][1] = s3c * y;
        s_sh[g][t][2] = s3c * z;
        s_sh[g][t][3] = s3c * x;
        s_sh[g][t][4] = s15 * x * y;
        s_sh[g][t][5] = s15 * y * z;
        s_sh[g][t][6] = 0.5f * s5 * (3.0f * z * z - 1.0f);
        s_sh[g][t][7] = s15 * x * z;
        s_sh[g][t][8] = 0.5f * s15 * (x * x - y * y);
        float xr = fminf(fmaxf(r * (1.0f / 6.0f), 0.0f), 1.0f);
        float gate = (r <= 6.0f) ? 2.8284271247461903f : 0.0f;
        #pragma unroll
        for (int jb = 0; jb < 8; ++jb) {
            float d = (xr - (float)jb * (1.0f / 7.0f)) * 7.0f;
            s_emb[g][t][jb] = expf(-0.5f * d * d) * gate;
        }
    }
    __syncthreads();

    float a0, a1, a2, a3;
    {
        const float bv = b0[t];
        a0 = bv; a1 = bv; a2 = bv; a3 = bv;
        #pragma unroll
        for (int c = 0; c < 8; ++c) {
            const float w = w0[c * 64 + t];
            a0 += s_emb[g][0][c] * w;
            a1 += s_emb[g][1][c] * w;
            a2 += s_emb[g][2][c] * w;
            a3 += s_emb[g][3][c] * w;
        }
        a0 = a0 / (1.0f + expf(-a0));
        a1 = a1 / (1.0f + expf(-a1));
        a2 = a2 / (1.0f + expf(-a2));
        a3 = a3 / (1.0f + expf(-a3));
        s_h0[g][0][t] = a0; s_h0[g][1][t] = a1;
        s_h0[g][2][t] = a2; s_h0[g][3][t] = a3;
    }
    __syncthreads();

    {
        const float bv = b1[t];
        a0 = bv; a1 = bv; a2 = bv; a3 = bv;
        #pragma unroll 4
        for (int c4 = 0; c4 < 16; ++c4) {
            const float wa = w1[(c4 * 4 + 0) * 64 + t];
            const float wb = w1[(c4 * 4 + 1) * 64 + t];
            const float wc = w1[(c4 * 4 + 2) * 64 + t];
            const float wd = w1[(c4 * 4 + 3) * 64 + t];
            float4 h;
            h = *reinterpret_cast<const float4*>(&s_h0[g][0][c4 * 4]);
            a0 += h.x * wa + h.y * wb + h.z * wc + h.w * wd;
            h = *reinterpret_cast<const float4*>(&s_h0[g][1][c4 * 4]);
            a1 += h.x * wa + h.y * wb + h.z * wc + h.w * wd;
            h = *reinterpret_cast<const float4*>(&s_h0[g][2][c4 * 4]);
            a2 += h.x * wa + h.y * wb + h.z * wc + h.w * wd;
            h = *reinterpret_cast<const float4*>(&s_h0[g][3][c4 * 4]);
            a3 += h.x * wa + h.y * wb + h.z * wc + h.w * wd;
        }
        a0 = a0 / (1.0f + expf(-a0));
        a1 = a1 / (1.0f + expf(-a1));
        a2 = a2 / (1.0f + expf(-a2));
        a3 = a3 / (1.0f + expf(-a3));
        s_h1[g][0][t] = a0; s_h1[g][1][t] = a1;
        s_h1[g][2][t] = a2; s_h1[g][3][t] = a3;
    }
    __syncthreads();

    {
        const float bv = b2[t];
        a0 = bv; a1 = bv; a2 = bv; a3 = bv;
        #pragma unroll 4
        for (int c4 = 0; c4 < 16; ++c4) {
            const float wa = w2[(c4 * 4 + 0) * 64 + t];
            const float wb = w2[(c4 * 4 + 1) * 64 + t];
            const float wc = w2[(c4 * 4 + 2) * 64 + t];
            const float wd = w2[(c4 * 4 + 3) * 64 + t];
            float4 h;
            h = *reinterpret_cast<const float4*>(&s_h1[g][0][c4 * 4]);
            a0 += h.x * wa + h.y * wb + h.z * wc + h.w * wd;
            h = *reinterpret_cast<const float4*>(&s_h1[g][1][c4 * 4]);
            a1 += h.x * wa + h.y * wb + h.z * wc + h.w * wd;
            h = *reinterpret_cast<const float4*>(&s_h1[g][2][c4 * 4]);
            a2 += h.x * wa + h.y * wb + h.z * wc + h.w * wd;
            h = *reinterpret_cast<const float4*>(&s_h1[g][3][c4 * 4]);
            a3 += h.x * wa + h.y * wb + h.z * wc + h.w * wd;
        }
        a0 = a0 / (1.0f + expf(-a0));
        a1 = a1 / (1.0f + expf(-a1));
        a2 = a2 / (1.0f + expf(-a2));
        a3 = a3 / (1.0f + expf(-a3));
    }

    float av[4] = {a0, a1, a2, a3};
    #pragma unroll
    for (int ei = 0; ei < 4; ++ei)
        g_Hh[(size_t)(eb + ei) * 64 + t] = __float2half(av[ei]);
    if (t < 36) {
        const int ei = t / 9, c = t % 9;
        g_sh[(size_t)(eb + ei) * 9 + c] = s_sh[g][ei][c];
    }
}

// ---------------- kernel B1: HMMA GEMM fp16, smem-staged stores ----------------
#define TPAD 72
#define SPAD 136

__global__ void __launch_bounds__(256) k_gemm_mma(
    const float* __restrict__ b3)
{
    __shared__ __half smemBuf[2 * 128 * TPAD];
    __half* sA = smemBuf;
    __half* sB = smemBuf + 128 * TPAD;

    const int t  = threadIdx.x;
    const int n0 = blockIdx.x * 128;
    const int e0 = blockIdx.y * 128;

    {
        const uint4* gA = reinterpret_cast<const uint4*>(g_Hh + (size_t)e0 * 64);
        const uint4* gB = reinterpret_cast<const uint4*>(g_w3T + (size_t)n0 * 64);
        #pragma unroll
        for (int i = 0; i < 4; ++i) {
            int lin = t + i * 256;
            int row = lin >> 3, c8 = lin & 7;
            int dst = row * TPAD + c8 * 8;
            *reinterpret_cast<uint4*>(sA + dst) = gA[lin];
            *reinterpret_cast<uint4*>(sB + dst) = gB[lin];
        }
    }
    __syncthreads();

    const int lane = t & 31, wid = t >> 5;
    const int wm = wid & 3, wn = wid >> 2;
    const int g  = lane >> 2, tg = lane & 3;

    float acc[2][8][4];
    #pragma unroll
    for (int mi = 0; mi < 2; ++mi)
        #pragma unroll
        for (int ni = 0; ni < 8; ++ni)
            #pragma unroll
            for (int q = 0; q < 4; ++q) acc[mi][ni][q] = 0.0f;

    #pragma unroll
    for (int ks = 0; ks < 4; ++ks) {
        const int k0 = ks * 16;
        uint32_t ah[2][4];
        #pragma unroll
        for (int mi = 0; mi < 2; ++mi) {
            const int base = (wm * 32 + mi * 16 + g) * TPAD + k0 + tg * 2;
            ah[mi][0] = *reinterpret_cast<const uint32_t*>(sA + base);
            ah[mi][1] = *reinterpret_cast<const uint32_t*>(sA + base + 8 * TPAD);
            ah[mi][2] = *reinterpret_cast<const uint32_t*>(sA + base + 8);
            ah[mi][3] = *reinterpret_cast<const uint32_t*>(sA + base + 8 * TPAD + 8);
        }
        #pragma unroll
        for (int ni = 0; ni < 8; ++ni) {
            const int base = (wn * 64 + ni * 8 + g) * TPAD + k0 + tg * 2;
            uint32_t bh[2];
            bh[0] = *reinterpret_cast<const uint32_t*>(sB + base);
            bh[1] = *reinterpret_cast<const uint32_t*>(sB + base + 8);
            #pragma unroll
            for (int mi = 0; mi < 2; ++mi)
                MMA_FP16(acc[mi][ni], ah[mi], bh);
        }
    }

    __syncthreads();
    {
        __half* sC = smemBuf;
        #pragma unroll
        for (int mi = 0; mi < 2; ++mi) {
            const int rl = wm * 32 + mi * 16 + g;
            #pragma unroll
            for (int ni = 0; ni < 8; ++ni) {
                const int cl = wn * 64 + ni * 8 + tg * 2;
                const float2 bb = __ldg(reinterpret_cast<const float2*>(b3 + n0 + cl));
                *reinterpret_cast<__half2*>(sC + rl * SPAD + cl) =
                    __floats2half2_rn(acc[mi][ni][0] + bb.x, acc[mi][ni][1] + bb.y);
                *reinterpret_cast<__half2*>(sC + (rl + 8) * SPAD + cl) =
                    __floats2half2_rn(acc[mi][ni][2] + bb.x, acc[mi][ni][3] + bb.y);
            }
        }
    }
    __syncthreads();
    {
        const __half* sC = smemBuf;
        #pragma unroll
        for (int i = 0; i < 8; ++i) {
            const int lin = t + i * 256;
            const int row = lin >> 4, q = lin & 15;
            const uint4 v = *reinterpret_cast<const uint4*>(sC + row * SPAD + q * 8);
            *reinterpret_cast<uint4*>(&g_Wv[(size_t)(e0 + row) * 2816 + n0 + q * 8]) = v;
        }
    }
}

// ---------------- kernel B2: T-contraction + scatter (div folded, 4 blocks/SM) ----
__global__ void __launch_bounds__(256, 4) k_tp2(
    const float* __restrict__ f_in,
    const int* __restrict__ esrc, const int* __restrict__ edst,
    float* __restrict__ out)
{
    __shared__ float sT[16][560];
    __shared__ float ssh[16][9];
    __shared__ int   ssrc[16];
    __shared__ int   sdst[16];
    __shared__ float sinv[16];

    const int tid = threadIdx.x;
    const int e0  = blockIdx.x << 4;

    if (tid < 144) ssh[tid / 9][tid % 9] = g_sh[(size_t)e0 * 9 + tid];
    if (tid < 16) ssrc[tid] = esrc[e0 + tid];
    else if (tid < 32) {
        const int d = edst[e0 + tid - 16];
        sdst[tid - 16] = d;
        sinv[tid - 16] = 1.0f / fmaxf(g_cnt[d], 1.0f);
    }
    __syncthreads();

    {
        const int e = tid >> 4, u = tid & 15;
        const float* x1 = f_in + (size_t)ssrc[e] * 144;
        float xall[9];
        xall[0] = x1[u];
        #pragma unroll
        for (int i = 0; i < 3; ++i) xall[1 + i] = x1[16 + i * 16 + u];
        #pragma unroll
        for (int i = 0; i < 5; ++i) xall[4 + i] = x1[64 + i * 16 + u];
        float sl[9];
        #pragma unroll
        for (int j = 0; j < 9; ++j) sl[j] = ssh[e][j];
        float* Te = sT[e];
        #pragma unroll
        for (int p = 0; p < 11; ++p) {
            const int l1 = PL1[p], l2 = PL2[p];
            const int d1 = 2 * l1 + 1, d2 = 2 * l2 + 1, d3 = PD3[p];
            float acc[5];
            #pragma unroll
            for (int k = 0; k < 5; ++k) acc[k] = 0.0f;
            const float* wj = g_w3j + W3OFF[p];
            #pragma unroll
            for (int i = 0; i < d1; ++i) {
                const float xi = xall[XO[l1] + i];
                #pragma unroll
                for (int j = 0; j < d2; ++j) {
                    const float xs = xi * sl[XO[l2] + j];
                    #pragma unroll
                    for (int k = 0; k < d3; ++k)
                        acc[k] += xs * __ldg(&wj[(i * d2 + j) * d3 + k]);
                }
            }
            #pragma unroll
            for (int k = 0; k < d3; ++k)
                Te[TOFF[p] + u * d3 + k] = ALPHA[p] * acc[k];
        }
    }
    __syncthreads();

    const int e  = tid >> 4;
    const int uh = (tid >> 2) & 3;
    const int wq = tid & 3;
    float4 acc[9];
    #pragma unroll
    for (int a = 0; a < 9; ++a) acc[a] = make_float4(0.f, 0.f, 0.f, 0.f);

    const __half* wvh = g_Wv + (size_t)(e0 + e) * 2816;
    const float* Te = sT[e];

    #pragma unroll
    for (int p = 0; p < 11; ++p) {
        const int d3 = PD3[p];
        #pragma unroll
        for (int ui = 0; ui < 4; ++ui) {
            const int u = uh * 4 + ui;
            const uint2 raw = *reinterpret_cast<const uint2*>(
                wvh + (p * 16 + u) * 16 + wq * 4);
            const float2 f0 = __half22float2(*reinterpret_cast<const __half2*>(&raw.x));
            const float2 f1 = __half22float2(*reinterpret_cast<const __half2*>(&raw.y));
            #pragma unroll
            for (int k = 0; k < d3; ++k) {
                const float tv = Te[TOFF[p] + u * d3 + k];
                const int a = AROW[p] + k;
                acc[a].x += tv * f0.x; acc[a].y += tv * f0.y;
                acc[a].z += tv * f1.x; acc[a].w += tv * f1.y;
            }
        }
    }

    #pragma unroll
    for (int a = 0; a < 9; ++a) {
        #pragma unroll
        for (int off = 4; off <= 8; off <<= 1) {
            acc[a].x += __shfl_xor_sync(0xffffffffu, acc[a].x, off);
            acc[a].y += __shfl_xor_sync(0xffffffffu, acc[a].y, off);
            acc[a].z += __shfl_xor_sync(0xffffffffu, acc[a].z, off);
            acc[a].w += __shfl_xor_sync(0xffffffffu, acc[a].w, off);
        }
    }
    if (uh == 0) {
        const float inv = sinv[e];
        float* op = out + (size_t)sdst[e] * 144 + (wq << 2);
        #pragma unroll
        for (int a = 0; a < 9; ++a) {
            atomicAdd(op + a * 16 + 0, acc[a].x * inv);
            atomicAdd(op + a * 16 + 1, acc[a].y * inv);
            atomicAdd(op + a * 16 + 2, acc[a].z * inv);
            atomicAdd(op + a * 16 + 3, acc[a].w * inv);
        }
    }
}

// ---------------- launch ----------------
extern "C" void kernel_launch(void* const* d_in, const int* in_sizes, int n_in,
                              void* d_out, int out_size)
{
    const float* f_in   = (const float*)d_in[0];
    const float* pos    = (const float*)d_in[1];
    const int*   batch  = (const int*)d_in[3];
    const int*   esrc   = (const int*)d_in[4];
    const int*   edst   = (const int*)d_in[5];
    const float* eshift = (const float*)d_in[6];
    const float* cell   = (const float*)d_in[7];
    const float* w0 = (const float*)d_in[8];
    const float* b0 = (const float*)d_in[9];
    const float* w1 = (const float*)d_in[10];
    const float* b1 = (const float*)d_in[11];
    const float* w2 = (const float*)d_in[12];
    const float* b2 = (const float*)d_in[13];
    const float* w3 = (const float*)d_in[14];
    const float* b3 = (const float*)d_in[15];
    float* out = (float*)d_out;

    const int setup_blocks = 11 + (NN * 144 + 511) / 512;
    k_setup<<<setup_blocks, 512>>>(w3, out);
    k_edge_mlp<<<NE / 16, 256>>>(pos, batch, esrc, edst, eshift, cell,
                                 w0, b0, w1, b1, w2, b2);
    k_gemm_mma<<<dim3(22, NE / 128), 256>>>(b3);
    k_tp2<<<NE / 16, 256>>>(f_in, esrc, edst, out);
}

// round 17
// speedup vs baseline: 1.4037x; 1.0556x over previous
#include <cuda_runtime.h>
#include <cuda_fp16.h>
#include <math.h>
#include <cstdint>

#define NE 160000
#define NN 10000

// ---------------- device scratch ----------------
__device__ __half g_Hh[(size_t)NE * 64];      // MLP hidden, fp16, [e][k]
__device__ __half g_w3T[(size_t)2816 * 64];   // w3 transposed [n][k], fp16
__device__ float g_sh[NE * 9];                // spherical harmonics
__device__ float g_cnt[NN];                   // per-node edge counts
__device__ float g_w3j[363];                  // Wigner-3j tables
__device__ __half g_Wv[(size_t)NE * 2816];    // per-edge weights (fp16, full)

// ---------------- path metadata ----------------
__device__ constexpr int PL1[11]   = {0,0,0,1,1,1,1,2,2,2,2};
__device__ constexpr int PL2[11]   = {0,1,2,0,1,1,2,0,1,2,2};
__device__ constexpr int PL3[11]   = {0,1,2,1,0,2,1,2,1,0,2};
__device__ constexpr int PD3[11]   = {1,3,5,3,1,5,3,5,3,1,5};
__device__ constexpr int W3OFF[11] = {0,1,10,35,44,53,98,143,168,213,238};
__device__ constexpr int TOFF[11]  = {0,16,64,144,192,208,288,336,416,464,480};
__device__ constexpr int AROW[11]  = {0,1,4,1,0,4,1,4,1,0,4};
__device__ constexpr float ALPHA[11] = {
    0.14433756729740643f, 0.21650635094610965f, 0.27950849718747373f,
    0.21650635094610965f, 0.14433756729740643f, 0.27950849718747373f,
    0.21650635094610965f, 0.27950849718747373f, 0.21650635094610965f,
    0.14433756729740643f, 0.27950849718747373f};
__device__ constexpr int XO[3] = {0,1,4};

// ---------------- mma.sync m16n8k16 fp16 -> fp32 ----------------
#define MMA_FP16(d, a, b) \
    asm volatile("mma.sync.aligned.m16n8k16.row.col.f32.f16.f16.f32 " \
        "{%0,%1,%2,%3}, {%4,%5,%6,%7}, {%8,%9}, {%0,%1,%2,%3};" \
        : "+f"((d)[0]), "+f"((d)[1]), "+f"((d)[2]), "+f"((d)[3]) \
        : "r"((a)[0]), "r"((a)[1]), "r"((a)[2]), "r"((a)[3]), \
          "r"((b)[0]), "r"((b)[1]))

// ---------------- W3J math (exact FP64 replica) ----------------
__device__ double dfact(int n) { double r = 1.0; for (int i = 2; i <= n; ++i) r *= (double)i; return r; }

__device__ double su2_cg(int j1, int m1, int j2, int m2, int j3, int m3) {
    if (m1 + m2 != m3) return 0.0;
    int vmin = 0;
    if (-j1 + j2 + m3 > vmin) vmin = -j1 + j2 + m3;
    if (-j1 + m1 > vmin)      vmin = -j1 + m1;
    int vmax = j2 + j3 + m1;
    if (j3 - j1 + j2 < vmax) vmax = j3 - j1 + j2;
    if (j3 + m3 < vmax)      vmax = j3 + m3;
    double C = sqrt((2.0 * j3 + 1.0) * dfact(j3 + j1 - j2) * dfact(j3 - j1 + j2) * dfact(j1 + j2 - j3)
                    / dfact(j1 + j2 + j3 + 1)
                    * dfact(j3 + m3) * dfact(j3 - m3)
                    / (dfact(j1 - m1) * dfact(j1 + m1) * dfact(j2 - m2) * dfact(j2 + m2)));
    double S = 0.0;
    for (int v = vmin; v <= vmax; ++v) {
        double sgn = ((v + j2 + m2) & 1) ? -1.0 : 1.0;
        S += sgn / dfact(v) * dfact(j2 + j3 + m1 - v) * dfact(j1 - m1 + v)
             / dfact(j3 - j1 + j2 - v) / dfact(j3 + m3 - v) / dfact(v + j1 - j2 - m3);
    }
    return C * S;
}

__device__ void qelem(int l, int r, int c, double& re, double& im) {
    int m = r - l;
    double vr = 0.0, vi = 0.0;
    const double is2 = 0.70710678118654752440;
    if (m < 0) {
        if (c == l - m) vr = is2;
        if (c == l + m) vi = -is2;
    } else if (m == 0) {
        if (c == l) vr = 1.0;
    } else {
        double sg = (m & 1) ? -1.0 : 1.0;
        if (c == l + m) vr = sg * is2;
        if (c == l - m) vi = sg * is2;
    }
    if (l == 1) { double t = vr; vr = vi; vi = -t; }
    else if (l == 2) { vr = -vr; vi = -vi; }
    re = vr; im = vi;
}

// ---------------- k_setup: w3j init (blocks 0..10) + zero/conv (blocks 11+) ----
__global__ void __launch_bounds__(512) k_setup(
    const float* __restrict__ w3, float* __restrict__ out)
{
    const int t = threadIdx.x;
    if (blockIdx.x < 11) {
        __shared__ double s_part[125 * 4];
        __shared__ double s_val[125];
        __shared__ double s_inv;
        const int p = blockIdx.x;
        const int l1 = PL1[p], l2 = PL2[p], l3 = PL3[p];
        const int d1 = 2 * l1 + 1, d2 = 2 * l2 + 1, d3 = 2 * l3 + 1;
        const int nel = d1 * d2 * d3;
        const int elem = t >> 2, part = t & 3;

        if (elem < nel) {
            const int j = elem / (d2 * d3);
            const int l = (elem / d3) % d2;
            const int m = elem % d3;
            double sre = 0.0;
            const int npair = d1 * d2;
            for (int pq = part; pq < npair; pq += 4) {
                const int i = pq / d2, k = pq % d2;
                const int n = (i - l1) + (k - l2) + l3;
                if (n < 0 || n >= d3) continue;
                const double cg = su2_cg(l1, i - l1, l2, k - l2, l3, n - l3);
                if (cg == 0.0) continue;
                double q1r, q1i, q2r, q2i, q3r, q3i;
                qelem(l1, i, j, q1r, q1i);
                qelem(l2, k, l, q2r, q2i);
                qelem(l3, n, m, q3r, q3i);
                q3i = -q3i;
                const double ar = q1r * q2r - q1i * q2i;
                const double ai = q1r * q2i + q1i * q2r;
                sre += (ar * q3r - ai * q3i) * cg;
            }
            s_part[elem * 4 + part] = sre;
        }
        __syncthreads();
        if (elem < nel && part == 0)
            s_val[elem] = s_part[elem * 4] + s_part[elem * 4 + 1]
                        + s_part[elem * 4 + 2] + s_part[elem * 4 + 3];
        __syncthreads();
        if (t == 0) {
            double n2 = 0.0;
            for (int q = 0; q < nel; ++q) n2 += s_val[q] * s_val[q];
            s_inv = 1.0 / sqrt(n2);
        }
        __syncthreads();
        if (elem < nel && part == 0)
            g_w3j[W3OFF[p] + elem] = (float)(s_val[elem] * s_inv);
    } else {
        const int i = (blockIdx.x - 11) * 512 + t;
        if (i < NN * 144) out[i] = 0.0f;
        if (i < NN) g_cnt[i] = 0.0f;
        if (i < 64 * 2816) {
            const int k = i / 2816, n = i % 2816;
            g_w3T[(size_t)n * 64 + k] = __float2half(w3[i]);
        }
    }
}

// ---------------- kernel A: geometry + radial + MLP (+edge count) ----------------
__global__ void __launch_bounds__(256) k_edge_mlp(
    const float* __restrict__ pos, const int* __restrict__ batch,
    const int* __restrict__ esrc, const int* __restrict__ edst,
    const float* __restrict__ eshift, const float* __restrict__ cell,
    const float* __restrict__ w0, const float* __restrict__ b0,
    const float* __restrict__ w1, const float* __restrict__ b1,
    const float* __restrict__ w2, const float* __restrict__ b2)
{
    __shared__ float s_sh[4][4][9];
    __shared__ float s_emb[4][4][8];
    __shared__ float s_h0[4][4][64];
    __shared__ float s_h1[4][4][64];
    const int g = threadIdx.x >> 6;
    const int t = threadIdx.x & 63;
    const int eb = blockIdx.x * 16 + g * 4;

    if (t < 4) {
        const int e = eb + t;
        const int src = esrc[e], dst = edst[e];
        atomicAdd(&g_cnt[dst], 1.0f);          // folded k_count
        const int b = batch[src];
        const float s0 = eshift[e * 3 + 0], s1 = eshift[e * 3 + 1], s2 = eshift[e * 3 + 2];
        const float* C = cell + b * 9;
        float vx = pos[dst * 3 + 0] - pos[src * 3 + 0] + s0 * C[0] + s1 * C[3] + s2 * C[6];
        float vy = pos[dst * 3 + 1] - pos[src * 3 + 1] + s0 * C[1] + s1 * C[4] + s2 * C[7];
        float vz = pos[dst * 3 + 2] - pos[src * 3 + 2] + s0 * C[2] + s1 * C[5] + s2 * C[8];
        float r = sqrtf(vx * vx + vy * vy + vz * vz + 1e-12f);
        float ir = 1.0f / r;
        float x = vx * ir, y = vy * ir, z = vz * ir;
        const float s3c = 1.7320508075688772f;
        const float s15 = 3.8729833462074170f;
        const float s5  = 2.2360679774997896f;
        s_sh[g][t][0] = 1.0f;
        s_sh[g][t][1] = s3c * y;
        s_sh[g][t][2] = s3c * z;
        s_sh[g][t][3] = s3c * x;
        s_sh[g][t][4] = s15 * x * y;
        s_sh[g][t][5] = s15 * y * z;
        s_sh[g][t][6] = 0.5f * s5 * (3.0f * z * z - 1.0f);
        s_sh[g][t][7] = s15 * x * z;
        s_sh[g][t][8] = 0.5f * s15 * (x * x - y * y);
        float xr = fminf(fmaxf(r * (1.0f / 6.0f), 0.0f), 1.0f);
        float gate = (r <= 6.0f) ? 2.8284271247461903f : 0.0f;
        #pragma unroll
        for (int jb = 0; jb < 8; ++jb) {
            float d = (xr - (float)jb * (1.0f / 7.0f)) * 7.0f;
            s_emb[g][t][jb] = expf(-0.5f * d * d) * gate;
        }
    }
    __syncthreads();

    float a0, a1, a2, a3;
    {
        const float bv = b0[t];
        a0 = bv; a1 = bv; a2 = bv; a3 = bv;
        #pragma unroll
        for (int c = 0; c < 8; ++c) {
            const float w = w0[c * 64 + t];
            a0 += s_emb[g][0][c] * w;
            a1 += s_emb[g][1][c] * w;
            a2 += s_emb[g][2][c] * w;
            a3 += s_emb[g][3][c] * w;
        }
        a0 = a0 / (1.0f + expf(-a0));
        a1 = a1 / (1.0f + expf(-a1));
        a2 = a2 / (1.0f + expf(-a2));
        a3 = a3 / (1.0f + expf(-a3));
        s_h0[g][0][t] = a0; s_h0[g][1][t] = a1;
        s_h0[g][2][t] = a2; s_h0[g][3][t] = a3;
    }
    __syncthreads();

    {
        const float bv = b1[t];
        a0 = bv; a1 = bv; a2 = bv; a3 = bv;
        #pragma unroll 4
        for (int c4 = 0; c4 < 16; ++c4) {
            const float wa = w1[(c4 * 4 + 0) * 64 + t];
            const float wb = w1[(c4 * 4 + 1) * 64 + t];
            const float wc = w1[(c4 * 4 + 2) * 64 + t];
            const float wd = w1[(c4 * 4 + 3) * 64 + t];
            float4 h;
            h = *reinterpret_cast<const float4*>(&s_h0[g][0][c4 * 4]);
            a0 += h.x * wa + h.y * wb + h.z * wc + h.w * wd;
            h = *reinterpret_cast<const float4*>(&s_h0[g][1][c4 * 4]);
            a1 += h.x * wa + h.y * wb + h.z * wc + h.w * wd;
            h = *reinterpret_cast<const float4*>(&s_h0[g][2][c4 * 4]);
            a2 += h.x * wa + h.y * wb + h.z * wc + h.w * wd;
            h = *reinterpret_cast<const float4*>(&s_h0[g][3][c4 * 4]);
            a3 += h.x * wa + h.y * wb + h.z * wc + h.w * wd;
        }
        a0 = a0 / (1.0f + expf(-a0));
        a1 = a1 / (1.0f + expf(-a1));
        a2 = a2 / (1.0f + expf(-a2));
        a3 = a3 / (1.0f + expf(-a3));
        s_h1[g][0][t] = a0; s_h1[g][1][t] = a1;
        s_h1[g][2][t] = a2; s_h1[g][3][t] = a3;
    }
    __syncthreads();

    {
        const float bv = b2[t];
        a0 = bv; a1 = bv; a2 = bv; a3 = bv;
        #pragma unroll 4
        for (int c4 = 0; c4 < 16; ++c4) {
            const float wa = w2[(c4 * 4 + 0) * 64 + t];
            const float wb = w2[(c4 * 4 + 1) * 64 + t];
            const float wc = w2[(c4 * 4 + 2) * 64 + t];
            const float wd = w2[(c4 * 4 + 3) * 64 + t];
            float4 h;
            h = *reinterpret_cast<const float4*>(&s_h1[g][0][c4 * 4]);
            a0 += h.x * wa + h.y * wb + h.z * wc + h.w * wd;
            h = *reinterpret_cast<const float4*>(&s_h1[g][1][c4 * 4]);
            a1 += h.x * wa + h.y * wb + h.z * wc + h.w * wd;
            h = *reinterpret_cast<const float4*>(&s_h1[g][2][c4 * 4]);
            a2 += h.x * wa + h.y * wb + h.z * wc + h.w * wd;
            h = *reinterpret_cast<const float4*>(&s_h1[g][3][c4 * 4]);
            a3 += h.x * wa + h.y * wb + h.z * wc + h.w * wd;
        }
        a0 = a0 / (1.0f + expf(-a0));
        a1 = a1 / (1.0f + expf(-a1));
        a2 = a2 / (1.0f + expf(-a2));
        a3 = a3 / (1.0f + expf(-a3));
    }

    float av[4] = {a0, a1, a2, a3};
    #pragma unroll
    for (int ei = 0; ei < 4; ++ei)
        g_Hh[(size_t)(eb + ei) * 64 + t] = __float2half(av[ei]);
    if (t < 36) {
        const int ei = t / 9, c = t % 9;
        g_sh[(size_t)(eb + ei) * 9 + c] = s_sh[g][ei][c];
    }
}

// ---------------- kernel B1: HMMA GEMM fp16, smem-staged stores ----------------
#define TPAD 72
#define SPAD 136

__global__ void __launch_bounds__(256) k_gemm_mma(
    const float* __restrict__ b3)
{
    __shared__ __half smemBuf[2 * 128 * TPAD];
    __half* sA = smemBuf;
    __half* sB = smemBuf + 128 * TPAD;

    const int t  = threadIdx.x;
    const int n0 = blockIdx.x * 128;
    const int e0 = blockIdx.y * 128;

    {
        const uint4* gA = reinterpret_cast<const uint4*>(g_Hh + (size_t)e0 * 64);
        const uint4* gB = reinterpret_cast<const uint4*>(g_w3T + (size_t)n0 * 64);
        #pragma unroll
        for (int i = 0; i < 4; ++i) {
            int lin = t + i * 256;
            int row = lin >> 3, c8 = lin & 7;
            int dst = row * TPAD + c8 * 8;
            *reinterpret_cast<uint4*>(sA + dst) = gA[lin];
            *reinterpret_cast<uint4*>(sB + dst) = gB[lin];
        }
    }
    __syncthreads();

    const int lane = t & 31, wid = t >> 5;
    const int wm = wid & 3, wn = wid >> 2;
    const int g  = lane >> 2, tg = lane & 3;

    float acc[2][8][4];
    #pragma unroll
    for (int mi = 0; mi < 2; ++mi)
        #pragma unroll
        for (int ni = 0; ni < 8; ++ni)
            #pragma unroll
            for (int q = 0; q < 4; ++q) acc[mi][ni][q] = 0.0f;

    #pragma unroll
    for (int ks = 0; ks < 4; ++ks) {
        const int k0 = ks * 16;
        uint32_t ah[2][4];
        #pragma unroll
        for (int mi = 0; mi < 2; ++mi) {
            const int base = (wm * 32 + mi * 16 + g) * TPAD + k0 + tg * 2;
            ah[mi][0] = *reinterpret_cast<const uint32_t*>(sA + base);
            ah[mi][1] = *reinterpret_cast<const uint32_t*>(sA + base + 8 * TPAD);
            ah[mi][2] = *reinterpret_cast<const uint32_t*>(sA + base + 8);
            ah[mi][3] = *reinterpret_cast<const uint32_t*>(sA + base + 8 * TPAD + 8);
        }
        #pragma unroll
        for (int ni = 0; ni < 8; ++ni) {
            const int base = (wn * 64 + ni * 8 + g) * TPAD + k0 + tg * 2;
            uint32_t bh[2];
            bh[0] = *reinterpret_cast<const uint32_t*>(sB + base);
            bh[1] = *reinterpret_cast<const uint32_t*>(sB + base + 8);
            #pragma unroll
            for (int mi = 0; mi < 2; ++mi)
                MMA_FP16(acc[mi][ni], ah[mi], bh);
        }
    }

    __syncthreads();
    {
        __half* sC = smemBuf;
        #pragma unroll
        for (int mi = 0; mi < 2; ++mi) {
            const int rl = wm * 32 + mi * 16 + g;
            #pragma unroll
            for (int ni = 0; ni < 8; ++ni) {
                const int cl = wn * 64 + ni * 8 + tg * 2;
                const float2 bb = __ldg(reinterpret_cast<const float2*>(b3 + n0 + cl));
                *reinterpret_cast<__half2*>(sC + rl * SPAD + cl) =
                    __floats2half2_rn(acc[mi][ni][0] + bb.x, acc[mi][ni][1] + bb.y);
                *reinterpret_cast<__half2*>(sC + (rl + 8) * SPAD + cl) =
                    __floats2half2_rn(acc[mi][ni][2] + bb.x, acc[mi][ni][3] + bb.y);
            }
        }
    }
    __syncthreads();
    {
        const __half* sC = smemBuf;
        #pragma unroll
        for (int i = 0; i < 8; ++i) {
            const int lin = t + i * 256;
            const int row = lin >> 4, q = lin & 15;
            const uint4 v = *reinterpret_cast<const uint4*>(sC + row * SPAD + q * 8);
            *reinterpret_cast<uint4*>(&g_Wv[(size_t)(e0 + row) * 2816 + n0 + q * 8]) = v;
        }
    }
}

// ---------------- kernel B2: T-contraction + scatter (w3j in smem) ----------------
__global__ void __launch_bounds__(256, 4) k_tp2(
    const float* __restrict__ f_in,
    const int* __restrict__ esrc, const int* __restrict__ edst,
    float* __restrict__ out)
{
    __shared__ float sT[16][560];
    __shared__ float ssh[16][9];
    __shared__ float sw3j[363];
    __shared__ int   ssrc[16];
    __shared__ int   sdst[16];
    __shared__ float sinv[16];

    const int tid = threadIdx.x;
    const int e0  = blockIdx.x << 4;

    if (tid < 144) ssh[tid / 9][tid % 9] = g_sh[(size_t)e0 * 9 + tid];
    if (tid < 16) ssrc[tid] = esrc[e0 + tid];
    else if (tid < 32) {
        const int d = edst[e0 + tid - 16];
        sdst[tid - 16] = d;
        sinv[tid - 16] = 1.0f / fmaxf(g_cnt[d], 1.0f);
    }
    for (int i = tid; i < 363; i += 256) sw3j[i] = g_w3j[i];
    __syncthreads();

    {
        const int e = tid >> 4, u = tid & 15;
        const float* x1 = f_in + (size_t)ssrc[e] * 144;
        float xall[9];
        xall[0] = x1[u];
        #pragma unroll
        for (int i = 0; i < 3; ++i) xall[1 + i] = x1[16 + i * 16 + u];
        #pragma unroll
        for (int i = 0; i < 5; ++i) xall[4 + i] = x1[64 + i * 16 + u];
        float sl[9];
        #pragma unroll
        for (int j = 0; j < 9; ++j) sl[j] = ssh[e][j];
        float* Te = sT[e];
        #pragma unroll
        for (int p = 0; p < 11; ++p) {
            const int l1 = PL1[p], l2 = PL2[p];
            const int d1 = 2 * l1 + 1, d2 = 2 * l2 + 1, d3 = PD3[p];
            float acc[5];
            #pragma unroll
            for (int k = 0; k < 5; ++k) acc[k] = 0.0f;
            const float* wj = sw3j + W3OFF[p];
            #pragma unroll
            for (int i = 0; i < d1; ++i) {
                const float xi = xall[XO[l1] + i];
                #pragma unroll
                for (int j = 0; j < d2; ++j) {
                    const float xs = xi * sl[XO[l2] + j];
                    #pragma unroll
                    for (int k = 0; k < d3; ++k)
                        acc[k] += xs * wj[(i * d2 + j) * d3 + k];
                }
            }
            #pragma unroll
            for (int k = 0; k < d3; ++k)
                Te[TOFF[p] + u * d3 + k] = ALPHA[p] * acc[k];
        }
    }
    __syncthreads();

    const int e  = tid >> 4;
    const int uh = (tid >> 2) & 3;
    const int wq = tid & 3;
    float4 acc[9];
    #pragma unroll
    for (int a = 0; a < 9; ++a) acc[a] = make_float4(0.f, 0.f, 0.f, 0.f);

    const __half* wvh = g_Wv + (size_t)(e0 + e) * 2816;
    const float* Te = sT[e];

    #pragma unroll
    for (int p = 0; p < 11; ++p) {
        const int d3 = PD3[p];
        #pragma unroll
        for (int ui = 0; ui < 4; ++ui) {
            const int u = uh * 4 + ui;
            const uint2 raw = *reinterpret_cast<const uint2*>(
                wvh + (p * 16 + u) * 16 + wq * 4);
            const float2 f0 = __half22float2(*reinterpret_cast<const __half2*>(&raw.x));
            const float2 f1 = __half22float2(*reinterpret_cast<const __half2*>(&raw.y));
            #pragma unroll
            for (int k = 0; k < d3; ++k) {
                const float tv = Te[TOFF[p] + u * d3 + k];
                const int a = AROW[p] + k;
                acc[a].x += tv * f0.x; acc[a].y += tv * f0.y;
                acc[a].z += tv * f1.x; acc[a].w += tv * f1.y;
            }
        }
    }

    #pragma unroll
    for (int a = 0; a < 9; ++a) {
        #pragma unroll
        for (int off = 4; off <= 8; off <<= 1) {
            acc[a].x += __shfl_xor_sync(0xffffffffu, acc[a].x, off);
            acc[a].y += __shfl_xor_sync(0xffffffffu, acc[a].y, off);
            acc[a].z += __shfl_xor_sync(0xffffffffu, acc[a].z, off);
            acc[a].w += __shfl_xor_sync(0xffffffffu, acc[a].w, off);
        }
    }
    if (uh == 0) {
        const float inv = sinv[e];
        float* op = out + (size_t)sdst[e] * 144 + (wq << 2);
        #pragma unroll
        for (int a = 0; a < 9; ++a) {
            atomicAdd(op + a * 16 + 0, acc[a].x * inv);
            atomicAdd(op + a * 16 + 1, acc[a].y * inv);
            atomicAdd(op + a * 16 + 2, acc[a].z * inv);
            atomicAdd(op + a * 16 + 3, acc[a].w * inv);
        }
    }
}

// ---------------- launch ----------------
extern "C" void kernel_launch(void* const* d_in, const int* in_sizes, int n_in,
                              void* d_out, int out_size)
{
    const float* f_in   = (const float*)d_in[0];
    const float* pos    = (const float*)d_in[1];
    const int*   batch  = (const int*)d_in[3];
    const int*   esrc   = (const int*)d_in[4];
    const int*   edst   = (const int*)d_in[5];
    const float* eshift = (const float*)d_in[6];
    const float* cell   = (const float*)d_in[7];
    const float* w0 = (const float*)d_in[8];
    const float* b0 = (const float*)d_in[9];
    const float* w1 = (const float*)d_in[10];
    const float* b1 = (const float*)d_in[11];
    const float* w2 = (const float*)d_in[12];
    const float* b2 = (const float*)d_in[13];
    const float* w3 = (const float*)d_in[14];
    const float* b3 = (const float*)d_in[15];
    float* out = (float*)d_out;

    const int setup_blocks = 11 + (NN * 144 + 511) / 512;
    k_setup<<<setup_blocks, 512>>>(w3, out);
    k_edge_mlp<<<NE / 16, 256>>>(pos, batch, esrc, edst, eshift, cell,
                                 w0, b0, w1, b1, w2, b2);
    k_gemm_mma<<<dim3(22, NE / 128), 256>>>(b3);
    k_tp2<<<NE / 16, 256>>>(f_in, esrc, edst, out);
}